// round 15
// baseline (speedup 1.0000x reference)
#include <cuda_runtime.h>
#include <cuda_fp16.h>
#include <math.h>
#include <stdint.h>

// ---------------------------------------------------------------------------
// AngleLinear (SphereFace A-Softmax forward, m=4, it=1) — fused mma.sync fp16
//   out[n,c] = clip( (x_n . w_c) / (|x_n| |w_c|), -1, 1 ) * |x_n|
//   out[n, target[n]] += (phi(c_t) - c_t) * |x_n| / (1 + lambda)
// R15: R14 with the alignment bug fixed (PBF 264 -> 272; 16B-aligned cp.async
// dst and float4 rows). wtrans fused into the GEMM: B cp.async'd from W as
// f32, converted f32->fp16 in SMEM one stage ahead (ldmatrix.trans b-path),
// per-column sum-of-squares accumulated in registers during conversion.
// 4 stages, 2 CTAs x 256 thr / SM. No W pre-pass.
// ---------------------------------------------------------------------------

#define PI_F 3.141592653f
#define INVL ((float)(1.0 / (1.0 + 1500.0 / 1.1)))

#define NMAX 512
#define DMAX 512

__device__ float g_xnorm[NMAX];
__device__ __half g_Ah[(size_t)NMAX * DMAX];  // x [n][d], fp16

// ---------------- PTX helpers (all sm_80-safe) ----------------
__device__ __forceinline__ uint32_t smem_u32(const void* p) {
    uint32_t a;
    asm("{ .reg .u64 t; cvta.to.shared.u64 t, %1; cvt.u32.u64 %0, t; }"
        : "=r"(a) : "l"(p));
    return a;
}
__device__ __forceinline__ void cp16(uint32_t dst, const void* src) {
    asm volatile("cp.async.cg.shared.global [%0], [%1], 16;"
                 :: "r"(dst), "l"(src));
}
#define CP_COMMIT() asm volatile("cp.async.commit_group;" ::: "memory")
#define CP_WAIT1() asm volatile("cp.async.wait_group 1;" ::: "memory")
#define CP_WAIT0() asm volatile("cp.async.wait_group 0;" ::: "memory")

__device__ __forceinline__ void ldsm4(uint32_t& r0, uint32_t& r1, uint32_t& r2,
                                      uint32_t& r3, uint32_t addr) {
    asm volatile("ldmatrix.sync.aligned.m8n8.x4.shared.b16 {%0,%1,%2,%3}, [%4];"
                 : "=r"(r0), "=r"(r1), "=r"(r2), "=r"(r3) : "r"(addr));
}
__device__ __forceinline__ void ldsm4t(uint32_t& r0, uint32_t& r1, uint32_t& r2,
                                       uint32_t& r3, uint32_t addr) {
    asm volatile(
        "ldmatrix.sync.aligned.m8n8.x4.trans.shared.b16 {%0,%1,%2,%3}, [%4];"
        : "=r"(r0), "=r"(r1), "=r"(r2), "=r"(r3) : "r"(addr));
}
__device__ __forceinline__ void mma16816(float* c, const uint32_t* a,
                                         uint32_t b0, uint32_t b1) {
    asm volatile(
        "mma.sync.aligned.m16n8k16.row.col.f32.f16.f16.f32 "
        "{%0,%1,%2,%3}, {%4,%5,%6,%7}, {%8,%9}, {%0,%1,%2,%3};"
        : "+f"(c[0]), "+f"(c[1]), "+f"(c[2]), "+f"(c[3])
        : "r"(a[0]), "r"(a[1]), "r"(a[2]), "r"(a[3]), "r"(b0), "r"(b1));
}

// ---------------- pre-pass: x f32 -> fp16 + row norms ----------------
__global__ void xprep_kernel(const float* __restrict__ X, int D) {
    __shared__ float red[4];
    const int r = blockIdx.x;
    const int tid = threadIdx.x;
    const float4 v = *reinterpret_cast<const float4*>(X + (size_t)r * D + tid * 4);
    __half2 h0 = __floats2half2_rn(v.x, v.y);
    __half2 h1 = __floats2half2_rn(v.z, v.w);
    uint2 u;
    u.x = *reinterpret_cast<const uint32_t*>(&h0);
    u.y = *reinterpret_cast<const uint32_t*>(&h1);
    *reinterpret_cast<uint2*>(&g_Ah[(size_t)r * D + tid * 4]) = u;
    float s = fmaf(v.x, v.x, fmaf(v.y, v.y, fmaf(v.z, v.z, v.w * v.w)));
#pragma unroll
    for (int o = 16; o > 0; o >>= 1) s += __shfl_down_sync(0xffffffffu, s, o);
    if ((tid & 31) == 0) red[tid >> 5] = s;
    __syncthreads();
    if (tid == 0)
        g_xnorm[r] = sqrtf((red[0] + red[1]) + (red[2] + red[3]));
}

// ---------------- epilogue math ----------------
__device__ __forceinline__ float epi_elem(float v, float rxn, float xn,
                                          float rwn, int c, long long tgt) {
    float cc = v * rxn * rwn;
    cc = fminf(1.0f, fmaxf(-1.0f, cc));
    float o = cc * xn;
    if ((long long)c == tgt) {
        float c2 = cc * cc;
        float cosm = fmaf(8.0f * c2, c2, fmaf(-8.0f, c2, 1.0f));
        float th = acosf(cc);
        float kf = floorf(th * (4.0f / PI_F));
        int ki = (int)kf;
        float sgn = (ki & 1) ? -1.0f : 1.0f;
        float phi = fmaf(sgn, cosm, -2.0f * kf);
        o += (phi - cc) * xn * INVL;
    }
    return o;
}

// ---------------- fused GEMM + convert + norms + epilogue ----------------
// BM=128, BN=64, BK=32. 256 threads = 8 warps (4x2), warp tile 32x32.
// A: fp16 cp.async, 4 stages, pitch 80 (normal ldmatrix).
// B: W f32 cp.async [k][c], 4 stages, pitch 272 (16B-aligned rows);
//    converted one stage ahead into 2 fp16 buffers [k][n] pitch 144
//    (ldmatrix.trans). 2 CTAs/SM.
#define BM 128
#define BN 64
#define BK 32
#define PA 80
#define PBF 272
#define PBH 144
#define A_ST (BM * PA)                     // 10240
#define BF_ST (BK * PBF)                   // 8704
#define BH_ST (BK * PBH)                   // 4608
#define STAGES 4
#define OFF_A 0
#define OFF_BF (STAGES * A_ST)             // 40960
#define OFF_BH (OFF_BF + STAGES * BF_ST)   // 75776
#define OFF_WN (OFF_BH + 2 * BH_ST)        // 84992
#define SM_TOTAL (OFF_WN + 256)            // 85248 -> 2 CTAs/SM

__device__ __forceinline__ void load_stage(uint32_t sb, const float* __restrict__ W,
                                           int slot, int m0, int c0, int it,
                                           int D, int C, int tid) {
    // A: 128 rows x 4 x 16B -> 2 per thread
    {
        const int r = tid >> 1;
        const int ch = (tid & 1) * 2;
#pragma unroll
        for (int q = 0; q < 2; q++)
            cp16(sb + OFF_A + (uint32_t)(slot * A_ST + r * PA + (ch + q) * 16),
                 g_Ah + (size_t)(m0 + r) * D + (size_t)it * BK + (ch + q) * 8);
    }
    // B f32: 32 rows x 16 x 16B -> 2 per thread (clamped at C edge)
    {
        const int k = tid >> 3;
        const int ch2 = (tid & 7) * 2;
#pragma unroll
        for (int q = 0; q < 2; q++) {
            int ceff = min(c0 + (ch2 + q) * 4, C - 4);
            cp16(sb + OFF_BF + (uint32_t)(slot * BF_ST + k * PBF + (ch2 + q) * 16),
                 W + (size_t)(it * BK + k) * C + ceff);
        }
    }
}

// Convert f32 stage -> fp16 buffer, accumulate per-column sum of squares.
// Thread t: rows 2*(t>>4), 2*(t>>4)+1; cols 4*(t&15)..+3.
__device__ __forceinline__ void convert_stage(char* smem, int slot, int buf,
                                              float* wn, int tid) {
    const int k2 = tid >> 4;
    const int ch = tid & 15;
    const char* src = smem + OFF_BF + slot * BF_ST + ch * 16;
    char* dst = smem + OFF_BH + buf * BH_ST + ch * 8;
    const float4 v0 = *reinterpret_cast<const float4*>(src + (2 * k2) * PBF);
    const float4 v1 = *reinterpret_cast<const float4*>(src + (2 * k2 + 1) * PBF);
    __half2 a0 = __floats2half2_rn(v0.x, v0.y);
    __half2 a1 = __floats2half2_rn(v0.z, v0.w);
    __half2 b0 = __floats2half2_rn(v1.x, v1.y);
    __half2 b1 = __floats2half2_rn(v1.z, v1.w);
    uint2 ua, ub;
    ua.x = *reinterpret_cast<uint32_t*>(&a0);
    ua.y = *reinterpret_cast<uint32_t*>(&a1);
    ub.x = *reinterpret_cast<uint32_t*>(&b0);
    ub.y = *reinterpret_cast<uint32_t*>(&b1);
    *reinterpret_cast<uint2*>(dst + (2 * k2) * PBH) = ua;
    *reinterpret_cast<uint2*>(dst + (2 * k2 + 1) * PBH) = ub;
    wn[0] = fmaf(v0.x, v0.x, fmaf(v1.x, v1.x, wn[0]));
    wn[1] = fmaf(v0.y, v0.y, fmaf(v1.y, v1.y, wn[1]));
    wn[2] = fmaf(v0.z, v0.z, fmaf(v1.z, v1.z, wn[2]));
    wn[3] = fmaf(v0.w, v0.w, fmaf(v1.w, v1.w, wn[3]));
}

__global__ void __launch_bounds__(256, 2)
gemm_epi_kernel(const float* __restrict__ W,
                const long long* __restrict__ TGT, float* __restrict__ OUT,
                int N, int D, int C) {
    extern __shared__ char smem[];
    const uint32_t sb = smem_u32(smem);
    float* swn = reinterpret_cast<float*>(smem + OFF_WN);
    const int tid = threadIdx.x;
    const int wid = tid >> 5;
    const int l = tid & 31;
    const int wm = wid >> 1;         // 0..3 -> rows 32*wm
    const int wn_ = wid & 1;         // 0..1 -> cols 32*wn_
    const int m0 = blockIdx.x * BM;  // x fastest: m-tiles share W tile in L2
    const int c0 = blockIdx.y * BN;

    // A ldmatrix (normal): rows 32wm + l%16, 16B col select by l/16
    const uint32_t a_off =
        (uint32_t)((32 * wm + (l & 15)) * PA + (l >> 4) * 16);
    // B ldmatrix.trans on [k][n]: row k=(l&7)+8*((l>>3)&1), col 32wn_+8*(l>>4)
    const uint32_t b_off =
        (uint32_t)(((l & 7) + 8 * ((l >> 3) & 1)) * PBH +
                   (32 * wn_ + ((l >> 4) * 8)) * 2);

    float acc[2][4][4];
#pragma unroll
    for (int i = 0; i < 2; i++)
#pragma unroll
        for (int j = 0; j < 4; j++)
#pragma unroll
            for (int q = 0; q < 4; q++) acc[i][j][q] = 0.0f;
    float wn[4] = {0.f, 0.f, 0.f, 0.f};

    if (tid < 64) swn[tid] = 0.0f;

    const int iters = D / BK;  // 16
    load_stage(sb, W, 0, m0, c0, 0, D, C, tid);
    CP_COMMIT();
    load_stage(sb, W, 1, m0, c0, 1, D, C, tid);
    CP_COMMIT();
    CP_WAIT1();          // group 0 (stage 0) resident
    __syncthreads();     // cross-thread visibility of stage 0 + swn zero
    convert_stage(smem, 0, 0, wn, tid);  // f32 stage 0 -> fp16 buf 0

    for (int it = 0; it < iters; it++) {
        if (it + 2 < iters) {
            // overwritten slots' readers finished >= 2 barriers ago
            load_stage(sb, W, (it + 2) % STAGES, m0, c0, it + 2, D, C, tid);
            CP_COMMIT();
            CP_WAIT1();      // group it+1 done (f32 B + A of stage it+1)
        } else {
            CP_WAIT0();      // drain tail
        }
        __syncthreads();     // fp16 buf (it) visible; stages safe

        if (it + 1 < iters)
            convert_stage(smem, (it + 1) % STAGES, (it + 1) & 1, wn, tid);

        const uint32_t abase = sb + (uint32_t)((it % STAGES) * A_ST);
        const uint32_t bbase = sb + OFF_BH + (uint32_t)((it & 1) * BH_ST);
#pragma unroll
        for (int ks = 0; ks < 2; ks++) {
            uint32_t ah[2][4];
            ldsm4(ah[0][0], ah[0][1], ah[0][2], ah[0][3],
                  abase + a_off + ks * 32);
            ldsm4(ah[1][0], ah[1][1], ah[1][2], ah[1][3],
                  abase + a_off + ks * 32 + 16 * PA);

            uint32_t bh[4][2];
            ldsm4t(bh[0][0], bh[0][1], bh[1][0], bh[1][1],
                   bbase + b_off + ks * (16 * PBH));
            ldsm4t(bh[2][0], bh[2][1], bh[3][0], bh[3][1],
                   bbase + b_off + ks * (16 * PBH) + 32);

#pragma unroll
            for (int i = 0; i < 2; i++)
#pragma unroll
                for (int j = 0; j < 4; j++)
                    mma16816(acc[i][j], ah[i], bh[j][0], bh[j][1]);
        }
    }

    // fold per-thread column norms (cols 4*(tid&15)..+3 of this c-tile)
    {
        const int cb = (tid & 15) * 4;
#pragma unroll
        for (int q = 0; q < 4; q++) atomicAdd(&swn[cb + q], wn[q]);
    }
    __syncthreads();

    // ---- epilogue ----
    const int base_m = m0 + 32 * wm + (l >> 2);
    float xns[2][2], rxns[2][2];
    long long tgs[2][2];
#pragma unroll
    for (int i = 0; i < 2; i++)
#pragma unroll
        for (int p = 0; p < 2; p++) {
            int row = base_m + 16 * i + 8 * p;  // always < N (N=512, BM exact)
            float xn = g_xnorm[row];
            xns[i][p] = xn;
            rxns[i][p] = 1.0f / xn;
            tgs[i][p] = TGT[row];
        }

#pragma unroll
    for (int j = 0; j < 4; j++) {
        const int cl = 32 * wn_ + 8 * j + 2 * (l & 3);
        const int c = c0 + cl;
        if (c >= C) continue;  // C even -> pair fully valid or fully out
        const float rw0 = rsqrtf(swn[cl]);
        const float rw1 = rsqrtf(swn[cl + 1]);
#pragma unroll
        for (int i = 0; i < 2; i++)
#pragma unroll
            for (int p = 0; p < 2; p++) {
                const int row = base_m + 16 * i + 8 * p;
                float2 o;
                o.x = epi_elem(acc[i][j][2 * p + 0], rxns[i][p], xns[i][p],
                               rw0, c, tgs[i][p]);
                o.y = epi_elem(acc[i][j][2 * p + 1], rxns[i][p], xns[i][p],
                               rw1, c + 1, tgs[i][p]);
                *reinterpret_cast<float2*>(&OUT[(size_t)row * C + c]) = o;
            }
    }
}

// ---------------------------------------------------------------------------
extern "C" void kernel_launch(void* const* d_in, const int* in_sizes, int n_in,
                              void* d_out, int out_size) {
    const float* x = (const float*)d_in[0];
    const long long* tgt = (const long long*)d_in[1];
    const float* w = (const float*)d_in[2];
    float* out = (float*)d_out;

    const int N = in_sizes[1];            // 512
    const int D = in_sizes[0] / N;        // 512
    const int C = in_sizes[2] / D;        // 100000

    xprep_kernel<<<N, 128>>>(x, D);

    cudaFuncSetAttribute(gemm_epi_kernel,
                         cudaFuncAttributeMaxDynamicSharedMemorySize, SM_TOTAL);
    dim3 grid((N + BM - 1) / BM, (C + BN - 1) / BN);
    gemm_epi_kernel<<<grid, 256, SM_TOTAL>>>(w, tgt, out, N, D, C);
}

// round 16
// speedup vs baseline: 1.1063x; 1.1063x over previous
#include <cuda_runtime.h>
#include <cuda_fp16.h>
#include <math.h>
#include <stdint.h>

// ---------------------------------------------------------------------------
// AngleLinear (SphereFace A-Softmax forward, m=4, it=1) — mma.sync fp16
//   out[n,c] = clip( (x_n . w_c) / (|x_n| |w_c|), -1, 1 ) * |x_n|
//   out[n, target[n]] += (phi(c_t) - c_t) * |x_n| / (1 + lambda)
// R16: revert fusion (R15 net-negative). R13 composition, but the GEMM runs
// TWO BK=32 stages per wait+barrier (6 stages, 2 CTAs x 256 thr / SM):
// 8 barriers instead of 16 -> halve the per-iteration sync/wait tax.
//   wtrans = R10 verbatim (49 us, LTS-cap), xprep = fused convert+norm.
// ---------------------------------------------------------------------------

#define PI_F 3.141592653f
#define INVL ((float)(1.0 / (1.0 + 1500.0 / 1.1)))

#define CMAX 100352
#define DMAX 512
#define NMAX 512

__device__ float g_wnorm2[CMAX];   // per-column sum of squares (atomic-folded)
__device__ float g_xnorm[NMAX];
__device__ __half g_Wh[(size_t)CMAX * DMAX];  // W^T [c][d], fp16
__device__ __half g_Ah[(size_t)NMAX * DMAX];  // x [n][d], fp16

// ---------------- PTX helpers (all sm_80-safe) ----------------
__device__ __forceinline__ uint32_t smem_u32(const void* p) {
    uint32_t a;
    asm("{ .reg .u64 t; cvta.to.shared.u64 t, %1; cvt.u32.u64 %0, t; }"
        : "=r"(a) : "l"(p));
    return a;
}
__device__ __forceinline__ void cp16(uint32_t dst, const void* src) {
    asm volatile("cp.async.cg.shared.global [%0], [%1], 16;"
                 :: "r"(dst), "l"(src));
}
#define CP_COMMIT() asm volatile("cp.async.commit_group;" ::: "memory")
#define CP_WAIT2() asm volatile("cp.async.wait_group 2;" ::: "memory")

__device__ __forceinline__ void ldsm4(uint32_t& r0, uint32_t& r1, uint32_t& r2,
                                      uint32_t& r3, uint32_t addr) {
    asm volatile("ldmatrix.sync.aligned.m8n8.x4.shared.b16 {%0,%1,%2,%3}, [%4];"
                 : "=r"(r0), "=r"(r1), "=r"(r2), "=r"(r3) : "r"(addr));
}
__device__ __forceinline__ void mma16816(float* c, const uint32_t* a,
                                         uint32_t b0, uint32_t b1) {
    asm volatile(
        "mma.sync.aligned.m16n8k16.row.col.f32.f16.f16.f32 "
        "{%0,%1,%2,%3}, {%4,%5,%6,%7}, {%8,%9}, {%0,%1,%2,%3};"
        : "+f"(c[0]), "+f"(c[1]), "+f"(c[2]), "+f"(c[3])
        : "r"(a[0]), "r"(a[1]), "r"(a[2]), "r"(a[3]), "r"(b0), "r"(b1));
}

// ---------------- pre-pass kernels ----------------
__global__ void zero_kernel() {
    int i = blockIdx.x * blockDim.x + threadIdx.x;
    if (i < CMAX) g_wnorm2[i] = 0.0f;
}

// x [N,D] f32 -> fp16 + row norm. One block (128 thr) per row.
__global__ void xprep_kernel(const float* __restrict__ X, int D) {
    __shared__ float red[4];
    const int r = blockIdx.x;
    const int tid = threadIdx.x;
    const float4 v = *reinterpret_cast<const float4*>(X + (size_t)r * D + tid * 4);
    __half2 h0 = __floats2half2_rn(v.x, v.y);
    __half2 h1 = __floats2half2_rn(v.z, v.w);
    uint2 u;
    u.x = *reinterpret_cast<const uint32_t*>(&h0);
    u.y = *reinterpret_cast<const uint32_t*>(&h1);
    *reinterpret_cast<uint2*>(&g_Ah[(size_t)r * D + tid * 4]) = u;
    float s = fmaf(v.x, v.x, fmaf(v.y, v.y, fmaf(v.z, v.z, v.w * v.w)));
#pragma unroll
    for (int o = 16; o > 0; o >>= 1) s += __shfl_down_sync(0xffffffffu, s, o);
    if ((tid & 31) == 0) red[tid >> 5] = s;
    __syncthreads();
    if (tid == 0)
        g_xnorm[r] = sqrtf((red[0] + red[1]) + (red[2] + red[3]));
}

// W [D,C] f32 -> W^T [C,D] fp16 (64x64 tiles through SMEM).
// Column sum-of-squares folded into the read phase; half2 writes.
// (R10 verbatim — measured 49 us, at LTS cap.)
__global__ void wtrans_kernel(const float* __restrict__ W, int D, int C) {
    __shared__ float s[64][65];
    __shared__ float sq[4][64];
    const int tid = threadIdx.x;
    const int c0 = blockIdx.x * 64;
    const int d0 = blockIdx.y * 64;

    const int cr = tid & 63;
    const int dr = tid >> 6;
    const int gc_r = c0 + cr;
    float acc = 0.0f;
#pragma unroll
    for (int i = 0; i < 16; i++) {
        int d = dr + 4 * i;
        float v = (gc_r < C) ? W[(size_t)(d0 + d) * C + gc_r] : 0.0f;
        s[d][cr] = v;
        acc = fmaf(v, v, acc);
    }
    sq[dr][cr] = acc;
    __syncthreads();

#pragma unroll
    for (int i = 0; i < 8; i++) {
        int e = tid + 256 * i;
        int c = e >> 5;
        int dp = (e & 31) * 2;
        int gc = c0 + c;
        if (gc < C) {
            __half2 h = __floats2half2_rn(s[dp][c], s[dp + 1][c]);
            *reinterpret_cast<__half2*>(&g_Wh[(size_t)gc * D + d0 + dp]) = h;
        }
    }
    if (tid < 64 && c0 + tid < C) {
        float t = (sq[0][tid] + sq[1][tid]) + (sq[2][tid] + sq[3][tid]);
        atomicAdd(&g_wnorm2[c0 + tid], t);
    }
}

// ---------------- epilogue math ----------------
__device__ __forceinline__ float epi_elem(float v, float rxn, float xn,
                                          float rwn, int c, long long tgt) {
    float cc = v * rxn * rwn;
    cc = fminf(1.0f, fmaxf(-1.0f, cc));
    float o = cc * xn;
    if ((long long)c == tgt) {
        float c2 = cc * cc;
        float cosm = fmaf(8.0f * c2, c2, fmaf(-8.0f, c2, 1.0f));
        float th = acosf(cc);
        float kf = floorf(th * (4.0f / PI_F));
        int ki = (int)kf;
        float sgn = (ki & 1) ? -1.0f : 1.0f;
        float phi = fmaf(sgn, cosm, -2.0f * kf);
        o += (phi - cc) * xn * INVL;
    }
    return o;
}

// ---------------- mma.sync GEMM + epilogue ----------------
// BM=128, BN=64, BK=32. 256 threads = 8 warps (4x2), warp tile 32x32.
// 6 stages, TWO stages per wait+barrier (8 barriers total). 2 CTAs/SM.
// Pitch 80 (conflict-free ldmatrix).
#define BM 128
#define BN 64
#define BK 32
#define PA 80
#define OFF_A 0
#define OFF_B (BM * PA)                   // 10240
#define STAGE_B (OFF_B + BN * PA)         // 15360 per stage
#define STAGES 6
#define SM_TOTAL (STAGES * STAGE_B)       // 92160 -> 2 CTAs/SM (184KB)

__device__ __forceinline__ void load_stage(uint32_t base, int m0, int c0,
                                           int it, int D, int tid) {
    // A: 128 rows x 4 chunks -> 2 per thread
    {
        const int r = tid >> 1;
        const int ch = (tid & 1) * 2;
#pragma unroll
        for (int q = 0; q < 2; q++)
            cp16(base + OFF_A + (uint32_t)(r * PA + (ch + q) * 16),
                 g_Ah + (size_t)(m0 + r) * D + (size_t)it * BK + (ch + q) * 8);
    }
    // B: 64 rows x 4 chunks -> 1 per thread (rows >= C read stale/zero g_Wh;
    // results for those columns are discarded in the epilogue)
    {
        const int r = tid >> 2;
        const int ch = tid & 3;
        cp16(base + OFF_B + (uint32_t)(r * PA + ch * 16),
             g_Wh + (size_t)(c0 + r) * D + (size_t)it * BK + ch * 8);
    }
}

__global__ void __launch_bounds__(256, 2)
gemm_epi_kernel(const long long* __restrict__ TGT, float* __restrict__ OUT,
                int N, int D, int C) {
    extern __shared__ char smem[];
    const uint32_t sb = smem_u32(smem);
    const int tid = threadIdx.x;
    const int wid = tid >> 5;
    const int l = tid & 31;
    const int wm = wid >> 1;         // 0..3 -> rows 32*wm
    const int wn = wid & 1;          // 0..1 -> cols 32*wn
    const int m0 = blockIdx.x * BM;  // x fastest: m-tiles share W tile in L2
    const int c0 = blockIdx.y * BN;

    // A ldmatrix (normal): rows 32wm + l%16, 16B col select by l/16
    const uint32_t a_off =
        (uint32_t)((32 * wm + (l & 15)) * PA + (l >> 4) * 16);
    // B ldmatrix (K-major): rows 32wn + l%8 + 8*(l/16), 16B col by (l>>3)&1
    const uint32_t b_off =
        (uint32_t)((32 * wn + (l & 7) + ((l >> 4) << 3)) * PA +
                   ((l >> 3) & 1) * 16);

    float acc[2][4][4];
#pragma unroll
    for (int i = 0; i < 2; i++)
#pragma unroll
        for (int j = 0; j < 4; j++)
#pragma unroll
            for (int q = 0; q < 4; q++) acc[i][j][q] = 0.0f;

    const int iters = D / BK;        // 16
    const int pairs = iters / 2;     // 8

    // prologue: stages 0..3 in flight (4 groups)
#pragma unroll
    for (int s = 0; s < 4; s++) {
        load_stage(sb + (uint32_t)(s * STAGE_B), m0, c0, s, D, tid);
        CP_COMMIT();
    }

    for (int p = 0; p < pairs; p++) {
        CP_WAIT2();          // stages 2p, 2p+1 resident (<=2 groups pending)
        __syncthreads();     // slots (2p+4)%6,(2p+5)%6: readers done last pair

        // issue next two stage loads (empty commits keep group count exact)
        if (2 * p + 4 < iters)
            load_stage(sb + (uint32_t)(((2 * p + 4) % STAGES) * STAGE_B),
                       m0, c0, 2 * p + 4, D, tid);
        CP_COMMIT();
        if (2 * p + 5 < iters)
            load_stage(sb + (uint32_t)(((2 * p + 5) % STAGES) * STAGE_B),
                       m0, c0, 2 * p + 5, D, tid);
        CP_COMMIT();

        // compute both stages of this pair
#pragma unroll
        for (int u = 0; u < 2; u++) {
            const uint32_t base =
                sb + (uint32_t)(((2 * p + u) % STAGES) * STAGE_B);
#pragma unroll
            for (int ks = 0; ks < 2; ks++) {
                const uint32_t ko = (uint32_t)(ks * 32);
                uint32_t ah[2][4];
                ldsm4(ah[0][0], ah[0][1], ah[0][2], ah[0][3],
                      base + OFF_A + a_off + ko);
                ldsm4(ah[1][0], ah[1][1], ah[1][2], ah[1][3],
                      base + OFF_A + a_off + ko + 16 * PA);

                uint32_t bh[4][2];
#pragma unroll
                for (int g = 0; g < 2; g++)
                    ldsm4(bh[2 * g][0], bh[2 * g][1], bh[2 * g + 1][0],
                          bh[2 * g + 1][1],
                          base + OFF_B + b_off + ko + (uint32_t)g * (16 * PA));

#pragma unroll
                for (int i = 0; i < 2; i++)
#pragma unroll
                    for (int j = 0; j < 4; j++)
                        mma16816(acc[i][j], ah[i], bh[j][0], bh[j][1]);
            }
        }
    }

    // ---- epilogue ----
    const int base_m = m0 + 32 * wm + (l >> 2);
    float xns[2][2], rxns[2][2];
    long long tgs[2][2];
#pragma unroll
    for (int i = 0; i < 2; i++)
#pragma unroll
        for (int p = 0; p < 2; p++) {
            int row = base_m + 16 * i + 8 * p;  // always < N (N=512, BM exact)
            float xn = g_xnorm[row];
            xns[i][p] = xn;
            rxns[i][p] = 1.0f / xn;
            tgs[i][p] = TGT[row];
        }

#pragma unroll
    for (int j = 0; j < 4; j++) {
        const int c = c0 + 32 * wn + 8 * j + 2 * (l & 3);
        if (c >= C) continue;  // C even -> pair fully valid or fully out
        const float rw0 = rsqrtf(g_wnorm2[c]);
        const float rw1 = rsqrtf(g_wnorm2[c + 1]);
#pragma unroll
        for (int i = 0; i < 2; i++)
#pragma unroll
            for (int p = 0; p < 2; p++) {
                const int row = base_m + 16 * i + 8 * p;
                float2 o;
                o.x = epi_elem(acc[i][j][2 * p + 0], rxns[i][p], xns[i][p],
                               rw0, c, tgs[i][p]);
                o.y = epi_elem(acc[i][j][2 * p + 1], rxns[i][p], xns[i][p],
                               rw1, c + 1, tgs[i][p]);
                *reinterpret_cast<float2*>(&OUT[(size_t)row * C + c]) = o;
            }
    }
}

// ---------------------------------------------------------------------------
extern "C" void kernel_launch(void* const* d_in, const int* in_sizes, int n_in,
                              void* d_out, int out_size) {
    const float* x = (const float*)d_in[0];
    const long long* tgt = (const long long*)d_in[1];
    const float* w = (const float*)d_in[2];
    float* out = (float*)d_out;

    const int N = in_sizes[1];            // 512
    const int D = in_sizes[0] / N;        // 512
    const int C = in_sizes[2] / D;        // 100000

    zero_kernel<<<(CMAX + 255) / 256, 256>>>();
    xprep_kernel<<<N, 128>>>(x, D);
    {
        dim3 tg2((C + 63) / 64, (D + 63) / 64);
        wtrans_kernel<<<tg2, 256>>>(w, D, C);
    }

    cudaFuncSetAttribute(gemm_epi_kernel,
                         cudaFuncAttributeMaxDynamicSharedMemorySize, SM_TOTAL);
    dim3 grid((N + BM - 1) / BM, (C + BN - 1) / BN);
    gemm_epi_kernel<<<grid, 256, SM_TOTAL>>>(tgt, out, N, D, C);
}

// round 17
// speedup vs baseline: 1.1222x; 1.0144x over previous
#include <cuda_runtime.h>
#include <cuda_fp16.h>
#include <math.h>
#include <stdint.h>

// ---------------------------------------------------------------------------
// AngleLinear (SphereFace A-Softmax forward, m=4, it=1) — mma.sync fp16
//   out[n,c] = clip( (x_n . w_c) / (|x_n| |w_c|), -1, 1 ) * |x_n|
//   out[n, target[n]] += (phi(c_t) - c_t) * |x_n| / (1 + lambda)
// R17: R13 skeleton (BK=32, 3-stage cp.async, BN=64, warp tile 32x32) with
// FRAGMENT DOUBLE-BUFFERING: next ks-step's ldmatrix issues before current
// step's MMAs, hiding LDSM latency under tensor issue (the R11-R16 evidence
// isolated the LDSM->MMA dependency chain as the binder).
// wtrans = R10 verbatim (49 us, LTS cap); xprep = fused convert+norm.
// ---------------------------------------------------------------------------

#define PI_F 3.141592653f
#define INVL ((float)(1.0 / (1.0 + 1500.0 / 1.1)))

#define CMAX 100352
#define DMAX 512
#define NMAX 512

__device__ float g_wnorm2[CMAX];   // per-column sum of squares (atomic-folded)
__device__ float g_xnorm[NMAX];
__device__ __half g_Wh[(size_t)CMAX * DMAX];  // W^T [c][d], fp16
__device__ __half g_Ah[(size_t)NMAX * DMAX];  // x [n][d], fp16

// ---------------- PTX helpers (all sm_80-safe) ----------------
__device__ __forceinline__ uint32_t smem_u32(const void* p) {
    uint32_t a;
    asm("{ .reg .u64 t; cvta.to.shared.u64 t, %1; cvt.u32.u64 %0, t; }"
        : "=r"(a) : "l"(p));
    return a;
}
__device__ __forceinline__ void cp16(uint32_t dst, const void* src) {
    asm volatile("cp.async.cg.shared.global [%0], [%1], 16;"
                 :: "r"(dst), "l"(src));
}
#define CP_COMMIT() asm volatile("cp.async.commit_group;" ::: "memory")
#define CP_WAIT1() asm volatile("cp.async.wait_group 1;" ::: "memory")

__device__ __forceinline__ void ldsm4(uint32_t& r0, uint32_t& r1, uint32_t& r2,
                                      uint32_t& r3, uint32_t addr) {
    asm volatile("ldmatrix.sync.aligned.m8n8.x4.shared.b16 {%0,%1,%2,%3}, [%4];"
                 : "=r"(r0), "=r"(r1), "=r"(r2), "=r"(r3) : "r"(addr));
}
__device__ __forceinline__ void mma16816(float* c, const uint32_t* a,
                                         uint32_t b0, uint32_t b1) {
    asm volatile(
        "mma.sync.aligned.m16n8k16.row.col.f32.f16.f16.f32 "
        "{%0,%1,%2,%3}, {%4,%5,%6,%7}, {%8,%9}, {%0,%1,%2,%3};"
        : "+f"(c[0]), "+f"(c[1]), "+f"(c[2]), "+f"(c[3])
        : "r"(a[0]), "r"(a[1]), "r"(a[2]), "r"(a[3]), "r"(b0), "r"(b1));
}

// ---------------- pre-pass kernels ----------------
__global__ void zero_kernel() {
    int i = blockIdx.x * blockDim.x + threadIdx.x;
    if (i < CMAX) g_wnorm2[i] = 0.0f;
}

// x [N,D] f32 -> fp16 + row norm. One block (128 thr) per row.
__global__ void xprep_kernel(const float* __restrict__ X, int D) {
    __shared__ float red[4];
    const int r = blockIdx.x;
    const int tid = threadIdx.x;
    const float4 v = *reinterpret_cast<const float4*>(X + (size_t)r * D + tid * 4);
    __half2 h0 = __floats2half2_rn(v.x, v.y);
    __half2 h1 = __floats2half2_rn(v.z, v.w);
    uint2 u;
    u.x = *reinterpret_cast<const uint32_t*>(&h0);
    u.y = *reinterpret_cast<const uint32_t*>(&h1);
    *reinterpret_cast<uint2*>(&g_Ah[(size_t)r * D + tid * 4]) = u;
    float s = fmaf(v.x, v.x, fmaf(v.y, v.y, fmaf(v.z, v.z, v.w * v.w)));
#pragma unroll
    for (int o = 16; o > 0; o >>= 1) s += __shfl_down_sync(0xffffffffu, s, o);
    if ((tid & 31) == 0) red[tid >> 5] = s;
    __syncthreads();
    if (tid == 0)
        g_xnorm[r] = sqrtf((red[0] + red[1]) + (red[2] + red[3]));
}

// W [D,C] f32 -> W^T [C,D] fp16 (64x64 tiles through SMEM).
// Column sum-of-squares folded into the read phase; half2 writes.
// (R10 verbatim — measured 49 us, at LTS cap.)
__global__ void wtrans_kernel(const float* __restrict__ W, int D, int C) {
    __shared__ float s[64][65];
    __shared__ float sq[4][64];
    const int tid = threadIdx.x;
    const int c0 = blockIdx.x * 64;
    const int d0 = blockIdx.y * 64;

    const int cr = tid & 63;
    const int dr = tid >> 6;
    const int gc_r = c0 + cr;
    float acc = 0.0f;
#pragma unroll
    for (int i = 0; i < 16; i++) {
        int d = dr + 4 * i;
        float v = (gc_r < C) ? W[(size_t)(d0 + d) * C + gc_r] : 0.0f;
        s[d][cr] = v;
        acc = fmaf(v, v, acc);
    }
    sq[dr][cr] = acc;
    __syncthreads();

#pragma unroll
    for (int i = 0; i < 8; i++) {
        int e = tid + 256 * i;
        int c = e >> 5;
        int dp = (e & 31) * 2;
        int gc = c0 + c;
        if (gc < C) {
            __half2 h = __floats2half2_rn(s[dp][c], s[dp + 1][c]);
            *reinterpret_cast<__half2*>(&g_Wh[(size_t)gc * D + d0 + dp]) = h;
        }
    }
    if (tid < 64 && c0 + tid < C) {
        float t = (sq[0][tid] + sq[1][tid]) + (sq[2][tid] + sq[3][tid]);
        atomicAdd(&g_wnorm2[c0 + tid], t);
    }
}

// ---------------- epilogue math ----------------
__device__ __forceinline__ float epi_elem(float v, float rxn, float xn,
                                          float rwn, int c, long long tgt) {
    float cc = v * rxn * rwn;
    cc = fminf(1.0f, fmaxf(-1.0f, cc));
    float o = cc * xn;
    if ((long long)c == tgt) {
        float c2 = cc * cc;
        float cosm = fmaf(8.0f * c2, c2, fmaf(-8.0f, c2, 1.0f));
        float th = acosf(cc);
        float kf = floorf(th * (4.0f / PI_F));
        int ki = (int)kf;
        float sgn = (ki & 1) ? -1.0f : 1.0f;
        float phi = fmaf(sgn, cosm, -2.0f * kf);
        o += (phi - cc) * xn * INVL;
    }
    return o;
}

// ---------------- mma.sync GEMM + epilogue ----------------
// BM=128, BN=64, BK=32. 256 threads = 8 warps (4x2), warp tile 32x32.
// 3 stages, fragment double-buffering (ldfrag for ks+1 before MMA of ks).
// Pitch 80 (conflict-free ldmatrix). 2 CTAs/SM (regs ~100).
#define BM 128
#define BN 64
#define BK 32
#define PA 80
#define OFF_A 0
#define OFF_B (BM * PA)                   // 10240
#define STAGE_B (OFF_B + BN * PA)         // 15360 per stage
#define STAGES 3
#define SM_TOTAL (STAGES * STAGE_B)       // 46080

__device__ __forceinline__ void load_stage(uint32_t base, int m0, int c0,
                                           int it, int D, int tid) {
    // A: 128 rows x 4 chunks -> 2 per thread
    {
        const int r = tid >> 1;
        const int ch = (tid & 1) * 2;
#pragma unroll
        for (int q = 0; q < 2; q++)
            cp16(base + OFF_A + (uint32_t)(r * PA + (ch + q) * 16),
                 g_Ah + (size_t)(m0 + r) * D + (size_t)it * BK + (ch + q) * 8);
    }
    // B: 64 rows x 4 chunks -> 1 per thread
    {
        const int r = tid >> 2;
        const int ch = tid & 3;
        cp16(base + OFF_B + (uint32_t)(r * PA + ch * 16),
             g_Wh + (size_t)(c0 + r) * D + (size_t)it * BK + ch * 8);
    }
}

__device__ __forceinline__ void ldfrag(uint32_t base, uint32_t a_off,
                                       uint32_t b_off, uint32_t ko,
                                       uint32_t ah[2][4], uint32_t bh[4][2]) {
    ldsm4(ah[0][0], ah[0][1], ah[0][2], ah[0][3], base + OFF_A + a_off + ko);
    ldsm4(ah[1][0], ah[1][1], ah[1][2], ah[1][3],
          base + OFF_A + a_off + ko + 16 * PA);
    ldsm4(bh[0][0], bh[0][1], bh[1][0], bh[1][1], base + OFF_B + b_off + ko);
    ldsm4(bh[2][0], bh[2][1], bh[3][0], bh[3][1],
          base + OFF_B + b_off + ko + 16 * PA);
}

__device__ __forceinline__ void mma_all(float acc[2][4][4],
                                        uint32_t ah[2][4], uint32_t bh[4][2]) {
#pragma unroll
    for (int i = 0; i < 2; i++)
#pragma unroll
        for (int j = 0; j < 4; j++)
            mma16816(acc[i][j], ah[i], bh[j][0], bh[j][1]);
}

__global__ void __launch_bounds__(256, 2)
gemm_epi_kernel(const long long* __restrict__ TGT, float* __restrict__ OUT,
                int N, int D, int C) {
    extern __shared__ char smem[];
    const uint32_t sb = smem_u32(smem);
    const int tid = threadIdx.x;
    const int wid = tid >> 5;
    const int l = tid & 31;
    const int wm = wid >> 1;         // 0..3 -> rows 32*wm
    const int wn = wid & 1;          // 0..1 -> cols 32*wn
    const int m0 = blockIdx.x * BM;  // x fastest: m-tiles share W tile in L2
    const int c0 = blockIdx.y * BN;

    // A ldmatrix (normal): rows 32wm + l%16, 16B col select by l/16
    const uint32_t a_off =
        (uint32_t)((32 * wm + (l & 15)) * PA + (l >> 4) * 16);
    // B ldmatrix (K-major): rows 32wn + l%8 + 8*(l/16), 16B col by (l>>3)&1
    const uint32_t b_off =
        (uint32_t)((32 * wn + (l & 7) + ((l >> 4) << 3)) * PA +
                   ((l >> 3) & 1) * 16);

    float acc[2][4][4];
#pragma unroll
    for (int i = 0; i < 2; i++)
#pragma unroll
        for (int j = 0; j < 4; j++)
#pragma unroll
            for (int q = 0; q < 4; q++) acc[i][j][q] = 0.0f;

    uint32_t ahA[2][4], bhA[4][2];   // fragment buffer A (current)
    uint32_t ahB[2][4], bhB[4][2];   // fragment buffer B (next)

    const int iters = D / BK;  // 16

    // prologue: stages 0,1 in flight; frags(it=0, ks=0) into buffer A
    load_stage(sb, m0, c0, 0, D, tid);
    CP_COMMIT();
    load_stage(sb + STAGE_B, m0, c0, 1, D, tid);
    CP_COMMIT();
    CP_WAIT1();          // stage 0 resident
    __syncthreads();
    ldfrag(sb, a_off, b_off, 0, ahA, bhA);

    for (int it = 0; it < iters; it++) {
        const uint32_t bcur = sb + (uint32_t)((it % STAGES) * STAGE_B);

        // --- ks = 0: prefetch ks=1 frags, issue next stage, MMA buffer A ---
        ldfrag(bcur, a_off, b_off, 32, ahB, bhB);
        if (it + 2 < iters)
            load_stage(sb + (uint32_t)(((it + 2) % STAGES) * STAGE_B),
                       m0, c0, it + 2, D, tid);
        CP_COMMIT();     // unconditional: keeps group counting exact
        mma_all(acc, ahA, bhA);

        // --- ks = 1: advance stage, prefetch next iter's ks=0, MMA buffer B ---
        if (it + 1 < iters) {
            CP_WAIT1();      // stage it+1 resident
            __syncthreads(); // slot (it+2)%3 safe: its readers finished at it-1
            ldfrag(sb + (uint32_t)(((it + 1) % STAGES) * STAGE_B),
                   a_off, b_off, 0, ahA, bhA);
        }
        mma_all(acc, ahB, bhB);
    }

    // ---- epilogue ----
    const int base_m = m0 + 32 * wm + (l >> 2);
    float xns[2][2], rxns[2][2];
    long long tgs[2][2];
#pragma unroll
    for (int i = 0; i < 2; i++)
#pragma unroll
        for (int p = 0; p < 2; p++) {
            int row = base_m + 16 * i + 8 * p;  // always < N (N=512, BM exact)
            float xn = g_xnorm[row];
            xns[i][p] = xn;
            rxns[i][p] = 1.0f / xn;
            tgs[i][p] = TGT[row];
        }

#pragma unroll
    for (int j = 0; j < 4; j++) {
        const int c = c0 + 32 * wn + 8 * j + 2 * (l & 3);
        if (c >= C) continue;  // C even -> pair fully valid or fully out
        const float rw0 = rsqrtf(g_wnorm2[c]);
        const float rw1 = rsqrtf(g_wnorm2[c + 1]);
#pragma unroll
        for (int i = 0; i < 2; i++)
#pragma unroll
            for (int p = 0; p < 2; p++) {
                const int row = base_m + 16 * i + 8 * p;
                float2 o;
                o.x = epi_elem(acc[i][j][2 * p + 0], rxns[i][p], xns[i][p],
                               rw0, c, tgs[i][p]);
                o.y = epi_elem(acc[i][j][2 * p + 1], rxns[i][p], xns[i][p],
                               rw1, c + 1, tgs[i][p]);
                *reinterpret_cast<float2*>(&OUT[(size_t)row * C + c]) = o;
            }
    }
}

// ---------------------------------------------------------------------------
extern "C" void kernel_launch(void* const* d_in, const int* in_sizes, int n_in,
                              void* d_out, int out_size) {
    const float* x = (const float*)d_in[0];
    const long long* tgt = (const long long*)d_in[1];
    const float* w = (const float*)d_in[2];
    float* out = (float*)d_out;

    const int N = in_sizes[1];            // 512
    const int D = in_sizes[0] / N;        // 512
    const int C = in_sizes[2] / D;        // 100000

    zero_kernel<<<(CMAX + 255) / 256, 256>>>();
    xprep_kernel<<<N, 128>>>(x, D);
    {
        dim3 tg2((C + 63) / 64, (D + 63) / 64);
        wtrans_kernel<<<tg2, 256>>>(w, D, C);
    }

    cudaFuncSetAttribute(gemm_epi_kernel,
                         cudaFuncAttributeMaxDynamicSharedMemorySize, SM_TOTAL);
    dim3 grid((N + BM - 1) / BM, (C + BN - 1) / BN);
    gemm_epi_kernel<<<grid, 256, SM_TOTAL>>>(tgt, out, N, D, C);
}